// round 13
// baseline (speedup 1.0000x reference)
#include <cuda_runtime.h>
#include <stdint.h>

// BasedKernel feature map, d=16:
//   out[row, 0]        = 1
//   out[row, 1..16]    = x[row, j-1] * 0.5
//   out[row, 17+idx]   = x[row, idx>>4] * x[row, idx&15] * SC2,  idx = 0..255
//
// R13: warp-autonomous TMA flush. Each warp computes 4 rows (4368B = the
// minimum 16B-multiple TMA transfer, = R12's proven granularity) into its
// own smem chunk, then __syncwarp + lane-0 fence/bulk-store/drain. NO
// block-wide barrier: warps flush and retire independently, so a warp's
// TMA drain overlaps sibling warps' compute in the same CTA slot. 4 warps
// per 128-thread block -> grid 16384 (4x fewer blocks than R12).

#define SC2 0.17677669529663687f

#define ROWS_PER_WARP  4
#define WARPS          4
#define THREADS        (WARPS * 32)                      // 128
#define FLOATS_PER_WARP (ROWS_PER_WARP * 273)           // 1092
#define BYTES_PER_WARP  (FLOATS_PER_WARP * 4)           // 4368, mult of 16
#define ROWS_PER_BLOCK  (ROWS_PER_WARP * WARPS)         // 16
#define FLOATS_PER_BLOCK (ROWS_PER_BLOCK * 273)         // 4368 floats

__global__ void __launch_bounds__(THREADS, 12)
based_feature_kernel(const float* __restrict__ x,
                     float* __restrict__ out)
{
    __shared__ __align__(16) float buf[FLOATS_PER_BLOCK];

    const int tid  = threadIdx.x;
    const int warp = tid >> 5;                 // 0..3
    const int lane = tid & 31;
    const int hi   = lane >> 4;                // 0 or 1
    const int k_lo = lane & 15;

    float* wbuf = buf + warp * FLOATS_PER_WARP;
    const int row_base = blockIdx.x * ROWS_PER_BLOCK + warp * ROWS_PER_WARP;

    // ---- Phase 1: this warp computes its 4 rows ----
#pragma unroll
    for (int r = 0; r < ROWS_PER_WARP; ++r) {
        const float* xr = x + (size_t)(row_base + r) * 16;
        float v = (lane < 16) ? __ldg(xr + lane) : 0.0f;

        float* o = wbuf + r * 273;

        // Convergent shfl (full warp participates).
        const float b2 = __shfl_sync(0xffffffffu, v, k_lo) * SC2;

        // Header (shfl-free, predicated stores only).
        if (lane < 16) o[1 + lane] = v * 0.5f;
        if (lane == 16) o[0] = 1.0f;

        // Quadratic: idx = 32m + lane, i = 2m + hi, k = lane&15.
#pragma unroll
        for (int m = 0; m < 8; ++m) {
            const float a = __shfl_sync(0xffffffffu, v, 2 * m + hi);
            o[17 + 32 * m + lane] = a * b2;
        }
    }

    // Make this warp's STS visible, then lane 0 flushes this warp's chunk.
    __syncwarp();

    if (lane == 0) {
        uint32_t saddr;
        asm volatile(
            "{ .reg .u64 t; cvta.to.shared.u64 t, %1; cvt.u32.u64 %0, t; }"
            : "=r"(saddr) : "l"(wbuf));

        float* g = out + (size_t)blockIdx.x * FLOATS_PER_BLOCK
                       + (size_t)warp * FLOATS_PER_WARP;

        asm volatile("fence.proxy.async.shared::cta;" ::: "memory");
        asm volatile(
            "cp.async.bulk.global.shared::cta.bulk_group [%0], [%1], %2;"
            :: "l"(g), "r"(saddr), "n"(BYTES_PER_WARP) : "memory");
        asm volatile("cp.async.bulk.commit_group;" ::: "memory");
        // Keep smem alive until the TMA engine has read this chunk.
        asm volatile("cp.async.bulk.wait_group.read 0;" ::: "memory");
    }
}

extern "C" void kernel_launch(void* const* d_in, const int* in_sizes, int n_in,
                              void* d_out, int out_size)
{
    const float* x = (const float*)d_in[0];
    float* out = (float*)d_out;

    const int n_rows = in_sizes[0] / 16;              // 262144
    const int blocks = n_rows / ROWS_PER_BLOCK;       // 16384 (exact)

    based_feature_kernel<<<blocks, THREADS>>>(x, out);
}

// round 14
// speedup vs baseline: 1.0322x; 1.0322x over previous
#include <cuda_runtime.h>
#include <stdint.h>

// BasedKernel feature map, d=16:
//   out[row, 0]        = 1
//   out[row, 1..16]    = x[row, j-1] * 0.5
//   out[row, 17+idx]   = x[row, idx>>4] * x[row, idx&15] * SC2,  idx = 0..255
//
// FINAL (= R12, best of 8 measured structural variants: 49.4us bench /
// 45.25us ncu, DRAM 67.8%, ~6.7 TB/s effective HBM stream = ~84% of spec,
// at the memory roofline).
//
// Key findings encoded here:
//  1. NO dynamically-indexed per-thread array: x stays one-value-per-lane;
//     dynamic indexing spills to local memory (LDL/STL) and was a hidden
//     l1tex ceiling worth 2x (164us -> ~82us equivalent).
//  2. Quadratic decomposition idx = 32m + lane -> i = 2m + (lane>>4),
//     k = lane&15: k-operand is ONE hoisted shfl premultiplied by SC2;
//     i-operand is one dynamic-source shfl per m (all shfls convergent).
//  3. Output staged in smem (contiguous conflict-free STS), flushed by a
//     single 1-D cp.async.bulk per block: the 286MB output stream never
//     touches L1 wavefront processing (worth another 2x vs STG).
//  4. Tile sweep: 4 rows/128 threads best (8:45.7, 16:48.5, 32:46.2 ncu-us);
//     4368B is the minimum legal bulk transfer. Losing variants: persistent
//     pipelined TMA, 2-tile double buffer, float4 STG flush, line-aligned
//     34944B TMA, warp-autonomous per-warp TMA.

#define SC2 0.17677669529663687f

#define ROWS_PER_BLOCK 4
#define THREADS        128
#define FLOATS_PER_BLOCK (ROWS_PER_BLOCK * 273)      // 1092
#define BYTES_PER_BLOCK  (FLOATS_PER_BLOCK * 4)      // 4368, multiple of 16

__global__ void __launch_bounds__(THREADS, 16)
based_feature_kernel(const float* __restrict__ x,
                     float* __restrict__ out)
{
    __shared__ __align__(16) float buf[FLOATS_PER_BLOCK];

    const int tid  = threadIdx.x;
    const int warp = tid >> 5;                 // 0..3 = local row
    const int lane = tid & 31;
    const int row  = blockIdx.x * ROWS_PER_BLOCK + warp;

    // ---- Phase 1: one row per warp, x resident one-value-per-lane ----
    const float* xr = x + (size_t)row * 16;
    float v = (lane < 16) ? __ldg(xr + lane) : 0.0f;

    float* o = buf + warp * 273;

    // Convergent shfls (full warp participates; never inside divergence).
    const float b2 = __shfl_sync(0xffffffffu, v, lane & 15) * SC2;  // k-operand
    const int   hi = lane >> 4;                                     // 0 or 1

    // Header (shfl-free, predicated stores only).
    if (lane < 16) o[1 + lane] = v * 0.5f;
    if (lane == 16) o[0] = 1.0f;

    // Quadratic part: idx = 32m + lane, i = 2m + hi, k = lane&15.
#pragma unroll
    for (int m = 0; m < 8; ++m) {
        const float a = __shfl_sync(0xffffffffu, v, 2 * m + hi);
        o[17 + 32 * m + lane] = a * b2;
    }

    __syncthreads();

    // ---- Phase 2: single 1-D TMA bulk store smem -> gmem (bypasses L1) ----
    if (tid == 0) {
        uint32_t saddr;
        asm volatile(
            "{ .reg .u64 t; cvta.to.shared.u64 t, %1; cvt.u32.u64 %0, t; }"
            : "=r"(saddr) : "l"(buf));

        float* g = out + (size_t)blockIdx.x * FLOATS_PER_BLOCK;
        const int nbytes = BYTES_PER_BLOCK;

        // Order generic-proxy smem writes before the async-proxy read.
        asm volatile("fence.proxy.async.shared::cta;" ::: "memory");
        asm volatile(
            "cp.async.bulk.global.shared::cta.bulk_group [%0], [%1], %2;"
            :: "l"(g), "r"(saddr), "r"(nbytes) : "memory");
        asm volatile("cp.async.bulk.commit_group;" ::: "memory");
        // Keep the CTA (and its smem) alive until the bulk read completes.
        asm volatile("cp.async.bulk.wait_group.read 0;" ::: "memory");
    }
}

extern "C" void kernel_launch(void* const* d_in, const int* in_sizes, int n_in,
                              void* d_out, int out_size)
{
    const float* x = (const float*)d_in[0];
    float* out = (float*)d_out;

    const int n_rows = in_sizes[0] / 16;              // 262144
    const int blocks = n_rows / ROWS_PER_BLOCK;       // 65536 (exact)

    based_feature_kernel<<<blocks, THREADS>>>(x, out);
}

// round 15
// speedup vs baseline: 1.1902x; 1.1530x over previous
#include <cuda_runtime.h>
#include <stdint.h>

// BasedKernel feature map, d=16:
//   out[row, 0]        = 1
//   out[row, 1..16]    = x[row, j-1] * 0.5
//   out[row, 17+idx]   = x[row, idx>>4] * x[row, idx&15] * SC2,  idx = 0..255
//
// R15 = R12 (best measured: 49.4us bench / 45.2us ncu, DRAM 68%) + an
// L2::evict_first cache-policy hint on the bulk store. The 286MB output is
// write-once-never-read: evict_first tells LTS to turn the lines around to
// DRAM immediately instead of retaining dead data. Zero structural change;
// degrades to R12 exactly if the hint has no effect.
//
// Proven structure: one warp per row (4 rows / 128 threads), x resident
// one-value-per-lane (no local-memory spill), hoisted-shfl quadratic
// (idx = 32m+lane -> i = 2m+(lane>>4), k = lane&15), smem staging with a
// single 1-D cp.async.bulk flush per block (output never touches L1).

#define SC2 0.17677669529663687f

#define ROWS_PER_BLOCK 4
#define THREADS        128
#define FLOATS_PER_BLOCK (ROWS_PER_BLOCK * 273)      // 1092
#define BYTES_PER_BLOCK  (FLOATS_PER_BLOCK * 4)      // 4368, multiple of 16

__global__ void __launch_bounds__(THREADS, 16)
based_feature_kernel(const float* __restrict__ x,
                     float* __restrict__ out)
{
    __shared__ __align__(16) float buf[FLOATS_PER_BLOCK];

    const int tid  = threadIdx.x;
    const int warp = tid >> 5;                 // 0..3 = local row
    const int lane = tid & 31;
    const int row  = blockIdx.x * ROWS_PER_BLOCK + warp;

    // ---- Phase 1: one row per warp, x resident one-value-per-lane ----
    const float* xr = x + (size_t)row * 16;
    float v = (lane < 16) ? __ldg(xr + lane) : 0.0f;

    float* o = buf + warp * 273;

    // Convergent shfls (full warp participates; never inside divergence).
    const float b2 = __shfl_sync(0xffffffffu, v, lane & 15) * SC2;  // k-operand
    const int   hi = lane >> 4;                                     // 0 or 1

    // Header (shfl-free, predicated stores only).
    if (lane < 16) o[1 + lane] = v * 0.5f;
    if (lane == 16) o[0] = 1.0f;

    // Quadratic part: idx = 32m + lane, i = 2m + hi, k = lane&15.
#pragma unroll
    for (int m = 0; m < 8; ++m) {
        const float a = __shfl_sync(0xffffffffu, v, 2 * m + hi);
        o[17 + 32 * m + lane] = a * b2;
    }

    __syncthreads();

    // ---- Phase 2: single 1-D TMA bulk store smem -> gmem (bypasses L1),
    //      with L2::evict_first policy on the write-once output stream ----
    if (tid == 0) {
        uint32_t saddr;
        asm volatile(
            "{ .reg .u64 t; cvta.to.shared.u64 t, %1; cvt.u32.u64 %0, t; }"
            : "=r"(saddr) : "l"(buf));

        float* g = out + (size_t)blockIdx.x * FLOATS_PER_BLOCK;
        const int nbytes = BYTES_PER_BLOCK;

        // Order generic-proxy smem writes before the async-proxy read.
        asm volatile("fence.proxy.async.shared::cta;" ::: "memory");
        asm volatile(
            "{\n\t"
            ".reg .b64 pol;\n\t"
            "createpolicy.fractional.L2::evict_first.b64 pol, 1.0;\n\t"
            "cp.async.bulk.global.shared::cta.bulk_group.L2::cache_hint "
            "[%0], [%1], %2, pol;\n\t"
            "}"
            :: "l"(g), "r"(saddr), "r"(nbytes) : "memory");
        asm volatile("cp.async.bulk.commit_group;" ::: "memory");
        // Keep the CTA (and its smem) alive until the bulk read completes.
        asm volatile("cp.async.bulk.wait_group.read 0;" ::: "memory");
    }
}

extern "C" void kernel_launch(void* const* d_in, const int* in_sizes, int n_in,
                              void* d_out, int out_size)
{
    const float* x = (const float*)d_in[0];
    float* out = (float*)d_out;

    const int n_rows = in_sizes[0] / 16;              // 262144
    const int blocks = n_rows / ROWS_PER_BLOCK;       // 65536 (exact)

    based_feature_kernel<<<blocks, THREADS>>>(x, out);
}